// round 1
// baseline (speedup 1.0000x reference)
#include <cuda_runtime.h>
#include <cstdint>

#define TT 4096
#define DD 2048
#define HH 8192
#define NE 8
#define RRK 16
#define ER 128
#define SCAL 2.0f

// ---------------- scratch (device globals; no allocation allowed) -------------
__device__ float g_W1r[(size_t)HH * DD];      // tf32-rounded W1  [H,D]
__device__ float g_W2r[(size_t)DD * HH];      // tf32-rounded W2  [D,H]
__device__ float g_B1r[(size_t)NE * HH * RRK];// tf32-rounded B1  [E,H,R]
__device__ float g_B2r[(size_t)NE * DD * RRK];// tf32-rounded B2  [E,D,R]
__device__ float g_Xr [(size_t)TT * DD];      // tf32-rounded x   [T,D]
__device__ float g_Y  [(size_t)TT * HH];      // gelu output (tf32-rounded) [T,H]
__device__ float g_Z1 [TT * ER];              // expanded lora z for fc1 [T,128]
__device__ float g_Z2 [TT * ER];              // expanded lora z for fc2 [T,128]

// ---------------- helpers ----------------------------------------------------
__device__ __forceinline__ float tf32r(float x) {
    uint32_t u;
    asm("cvt.rna.tf32.f32 %0, %1;" : "=r"(u) : "f"(x));
    return __uint_as_float(u);
}

__device__ __forceinline__ void cp16(uint32_t s, const void* g) {
    asm volatile("cp.async.ca.shared.global [%0], [%1], 16;" :: "r"(s), "l"(g));
}

__device__ __forceinline__ void mma_tf32(float* c, const uint32_t* a, const uint32_t* b) {
    asm volatile(
        "mma.sync.aligned.m16n8k8.row.col.f32.tf32.tf32.f32 "
        "{%0,%1,%2,%3}, {%4,%5,%6,%7}, {%8,%9}, {%0,%1,%2,%3};"
        : "+f"(c[0]), "+f"(c[1]), "+f"(c[2]), "+f"(c[3])
        : "r"(a[0]), "r"(a[1]), "r"(a[2]), "r"(a[3]), "r"(b[0]), "r"(b[1]));
}

__device__ __forceinline__ float gelu_new_f(float x) {
    float x3 = x * x * x;
    float inner = 0.7978845608028654f * (x + 0.044715f * x3);
    return 0.5f * x * (1.0f + tanhf(inner));
}

// ---------------- tf32 rounding copy -----------------------------------------
__global__ void round_tf32_k(float* __restrict__ dst, const float* __restrict__ src, int n4) {
    int i = blockIdx.x * blockDim.x + threadIdx.x;
    if (i < n4) {
        float4 v = reinterpret_cast<const float4*>(src)[i];
        v.x = tf32r(v.x); v.y = tf32r(v.y); v.z = tf32r(v.z); v.w = tf32r(v.w);
        reinterpret_cast<float4*>(dst)[i] = v;
    }
}

// ---------------- per-token rank-16 lora z: Z[t, e*16+r] ----------------------
// one block per token, 16 warps = 16 ranks; dot over KD
template<int KD>
__global__ void lora_z_k(const float* __restrict__ X, const float* __restrict__ A,
                         const int* __restrict__ eidx, float* __restrict__ Z) {
    int t = blockIdx.x;
    int e = eidx[t];
    int lane = threadIdx.x & 31, w = threadIdx.x >> 5;
    if (threadIdx.x < ER) Z[t * ER + threadIdx.x] = 0.f;
    __syncthreads();
    const float* a = A + ((size_t)e * RRK + w) * KD;
    const float* x = X + (size_t)t * KD;
    float s = 0.f;
    for (int i = lane * 4; i < KD; i += 128) {
        float4 xv = *reinterpret_cast<const float4*>(x + i);
        float4 av = *reinterpret_cast<const float4*>(a + i);
        s += xv.x * av.x + xv.y * av.y + xv.z * av.z + xv.w * av.w;
    }
    #pragma unroll
    for (int o = 16; o; o >>= 1) s += __shfl_xor_sync(0xffffffffu, s, o);
    if (lane == 0) Z[t * ER + e * RRK + w] = tf32r(SCAL * s);
}

// ---------------- fused GEMM: C[T,N] = [A0|AL] @ [W|BL]^T (+bias, opt. gelu) --
// A0:[T,K0], AL:[T,128]; W:[N,K0] row-major (W1/W2 natural layout);
// BL:[E,N,16] (B1/B2 natural layout). K total = K0+128.
#define BM 128
#define BN 128
#define BK 32
#define SKW 36          // smem row stride in words (conflict-free: 4*grp+tig)
#define SBUF 4608       // 128*36 words per buffer

template<int K0, bool GELU>
__global__ void __launch_bounds__(256, 2)
moe_gemm_k(const float* __restrict__ A0, const float* __restrict__ AL,
           const float* __restrict__ W,  const float* __restrict__ BL,
           const float* __restrict__ bias, float* __restrict__ C, int Nsz) {
    extern __shared__ float smem[];           // [As0|As1|Bs0|Bs1], 73728 B
    const int NK = (K0 + ER) / BK;
    const int m0 = blockIdx.y * BM, n0 = blockIdx.x * BN;
    const int tid  = threadIdx.x;
    const int lr   = tid >> 3, lc = tid & 7;  // loader: 32 rows x 8 float4-cols
    const int warp = tid >> 5, wm = warp >> 2, wn = warp & 3;
    const int lane = tid & 31, grp = lane >> 2, tig = lane & 3;

    float acc[4][4][4];
    #pragma unroll
    for (int i = 0; i < 4; i++)
        #pragma unroll
        for (int j = 0; j < 4; j++)
            #pragma unroll
            for (int c = 0; c < 4; c++) acc[i][j][c] = 0.f;

    uint32_t sA = (uint32_t)__cvta_generic_to_shared(smem);
    uint32_t sB = sA + 2 * SBUF * 4;

    auto load_tiles = [&](int kt, int buf) {
        int kk = kt * BK + 4 * lc;
        #pragma unroll
        for (int p = 0; p < 4; p++) {
            int row = lr + p * 32;
            const float* gp = (kk < K0)
                ? A0 + (size_t)(m0 + row) * K0 + kk
                : AL + (size_t)(m0 + row) * ER + (kk - K0);
            cp16(sA + (uint32_t)(buf * SBUF + row * SKW + 4 * lc) * 4, gp);
        }
        #pragma unroll
        for (int p = 0; p < 4; p++) {
            int nr = lr + p * 32;
            const float* gp;
            if (kk < K0) {
                gp = W + (size_t)(n0 + nr) * K0 + kk;
            } else {
                int j = kk - K0;                       // j in [0,128): e=j>>4, r=j&15
                gp = BL + ((size_t)(j >> 4) * Nsz + (n0 + nr)) * RRK + (j & 15);
            }
            cp16(sB + (uint32_t)(buf * SBUF + nr * SKW + 4 * lc) * 4, gp);
        }
    };

    load_tiles(0, 0);
    asm volatile("cp.async.commit_group;");
    load_tiles(1, 1);
    asm volatile("cp.async.commit_group;");

    for (int kt = 0; kt < NK; ++kt) {
        asm volatile("cp.async.wait_group 1;");
        __syncthreads();
        int buf = kt & 1;
        const float* As = smem + buf * SBUF;
        const float* Bs = smem + 2 * SBUF + buf * SBUF;
        #pragma unroll
        for (int s = 0; s < 4; s++) {
            uint32_t af[4][4], bf[4][2];
            int k = s * 8 + tig;
            #pragma unroll
            for (int i = 0; i < 4; i++) {
                int m = wm * 64 + i * 16 + grp;
                af[i][0] = __float_as_uint(As[m * SKW + k]);
                af[i][1] = __float_as_uint(As[(m + 8) * SKW + k]);
                af[i][2] = __float_as_uint(As[m * SKW + k + 4]);
                af[i][3] = __float_as_uint(As[(m + 8) * SKW + k + 4]);
            }
            #pragma unroll
            for (int j = 0; j < 4; j++) {
                int n = wn * 32 + j * 8 + grp;
                bf[j][0] = __float_as_uint(Bs[n * SKW + k]);
                bf[j][1] = __float_as_uint(Bs[n * SKW + k + 4]);
            }
            #pragma unroll
            for (int i = 0; i < 4; i++)
                #pragma unroll
                for (int j = 0; j < 4; j++)
                    mma_tf32(acc[i][j], af[i], bf[j]);
        }
        __syncthreads();
        if (kt + 2 < NK) load_tiles(kt + 2, buf);
        asm volatile("cp.async.commit_group;");
    }

    // epilogue
    #pragma unroll
    for (int i = 0; i < 4; i++) {
        int t0 = m0 + wm * 64 + i * 16 + grp;
        #pragma unroll
        for (int j = 0; j < 4; j++) {
            int n = n0 + wn * 32 + j * 8 + 2 * tig;
            float bv0 = bias[n], bv1 = bias[n + 1];
            float2 v0, v1;
            if (GELU) {
                v0.x = tf32r(gelu_new_f(acc[i][j][0] + bv0));
                v0.y = tf32r(gelu_new_f(acc[i][j][1] + bv1));
                v1.x = tf32r(gelu_new_f(acc[i][j][2] + bv0));
                v1.y = tf32r(gelu_new_f(acc[i][j][3] + bv1));
            } else {
                v0.x = acc[i][j][0] + bv0; v0.y = acc[i][j][1] + bv1;
                v1.x = acc[i][j][2] + bv0; v1.y = acc[i][j][3] + bv1;
            }
            *reinterpret_cast<float2*>(&C[(size_t)t0 * Nsz + n]) = v0;
            *reinterpret_cast<float2*>(&C[(size_t)(t0 + 8) * Nsz + n]) = v1;
        }
    }
}

// ---------------- launch ------------------------------------------------------
extern "C" void kernel_launch(void* const* d_in, const int* in_sizes, int n_in,
                              void* d_out, int out_size) {
    const float* x  = (const float*)d_in[0];
    const int*   ei = (const int*)  d_in[1];
    const float* W1 = (const float*)d_in[2];
    const float* b1 = (const float*)d_in[3];
    const float* A1 = (const float*)d_in[4];
    const float* B1 = (const float*)d_in[5];
    const float* W2 = (const float*)d_in[6];
    const float* b2 = (const float*)d_in[7];
    const float* A2 = (const float*)d_in[8];
    const float* B2 = (const float*)d_in[9];
    float* out = (float*)d_out;

    float *pW1r, *pW2r, *pB1r, *pB2r, *pXr, *pY, *pZ1, *pZ2;
    cudaGetSymbolAddress((void**)&pW1r, g_W1r);
    cudaGetSymbolAddress((void**)&pW2r, g_W2r);
    cudaGetSymbolAddress((void**)&pB1r, g_B1r);
    cudaGetSymbolAddress((void**)&pB2r, g_B2r);
    cudaGetSymbolAddress((void**)&pXr,  g_Xr);
    cudaGetSymbolAddress((void**)&pY,   g_Y);
    cudaGetSymbolAddress((void**)&pZ1,  g_Z1);
    cudaGetSymbolAddress((void**)&pZ2,  g_Z2);

    cudaFuncSetAttribute(moe_gemm_k<DD, true>,
                         cudaFuncAttributeMaxDynamicSharedMemorySize, 73728);
    cudaFuncSetAttribute(moe_gemm_k<HH, false>,
                         cudaFuncAttributeMaxDynamicSharedMemorySize, 73728);

    int n4;
    n4 = HH * DD / 4;        round_tf32_k<<<(n4 + 255) / 256, 256>>>(pW1r, W1, n4);
    n4 = DD * HH / 4;        round_tf32_k<<<(n4 + 255) / 256, 256>>>(pW2r, W2, n4);
    n4 = NE * HH * RRK / 4;  round_tf32_k<<<(n4 + 255) / 256, 256>>>(pB1r, B1, n4);
    n4 = NE * DD * RRK / 4;  round_tf32_k<<<(n4 + 255) / 256, 256>>>(pB2r, B2, n4);
    n4 = TT * DD / 4;        round_tf32_k<<<(n4 + 255) / 256, 256>>>(pXr,  x,  n4);

    lora_z_k<DD><<<TT, 512>>>(x, A1, ei, pZ1);

    moe_gemm_k<DD, true><<<dim3(HH / BN, TT / BM), 256, 73728>>>(
        pXr, pZ1, pW1r, pB1r, b1, pY, HH);

    lora_z_k<HH><<<TT, 512>>>(pY, A2, ei, pZ2);

    moe_gemm_k<HH, false><<<dim3(DD / BN, TT / BM), 256, 73728>>>(
        pY, pZ2, pW2r, pB2r, b2, out, DD);
}